// round 15
// baseline (speedup 1.0000x reference)
#include <cuda_runtime.h>

// Problem constants
#define NPT   4096      // B*H*W = 4*32*32 output points
#define NOC   64        // output channels
#define NFEAT 576       // IC*K*K unfolded features
#define NGRP  144       // 4-feature groups
#define NGRP_PAD 160    // padded so prefetch beyond last chunk stays in bounds
#define NCH   5         // subarray chunks (29,29,29,29,28 groups)
#define OBLK  2         // output channels per block in main kernel
#define PTB   128       // points per block (threads)
#define NW    (NOC * NFEAT)   // 36864 weight elements
#define QTOT  (4 * 64 * 34 * 34)   // haloed quantized input bytes

// Scratch (no allocations allowed -> device globals)
__device__ float    g_maxabs;
__device__ unsigned g_wpos[NOC * NFEAT];        // [o][t][g]
__device__ unsigned g_wneg[NOC * NFEAT];
__device__ unsigned char g_q[QTOT];             // [b][c][y+1][x+1], halo = 0
__device__ uint4    g_sv2[NGRP_PAD * NPT];      // [g][pt]; pads never consumed
__device__ int      g_acc[NOC * NPT];           // atomically accumulated diffs

// ------------- quantize once per pixel (haloed) + zero accumulator
#define QB ((QTOT + 255) / 256)                    // 1156
#define ZB (NOC * NPT / (256 * 4))                 // 256
__global__ void k_quant(const float* __restrict__ x) {
    int id = blockIdx.x * 256 + threadIdx.x;
    if (blockIdx.x < QB) {
        if (id >= QTOT) return;
        int col = id % 34;
        int row = (id / 34) % 34;
        int bc  = id / (34 * 34);          // b*64 + c
        unsigned char q = 0;
        int y = row - 1, xx = col - 1;
        if ((unsigned)y < 32u && (unsigned)xx < 32u) {
            float v = x[(bc * 32 + y) * 32 + xx];
            v = fminf(fmaxf(v, -8.f), 7.9375f);
            q = (unsigned char)(((int)rintf(v * 16.f)) & 255);
        }
        g_q[id] = q;
    } else {
        int zid = (blockIdx.x - QB) * 256 + threadIdx.x;
        if (zid < NOC * NPT / 4)
            *(int4*)&g_acc[zid * 4] = make_int4(0, 0, 0, 0);
    }
}

// ---------------- fused prep: maxabs + weight slicing + stream packing
#define WB ((NOC * NGRP + 255) / 256)              // 36
#define SB ((NPT * NGRP + 255) / 256)              // 2304
__global__ void k_prep(const float* __restrict__ w) {
    if (blockIdx.x < WB) {
        // ---- per-block maxabs reduction over the full weight tensor ----
        __shared__ float red[32];
        __shared__ float s_ma;
        float m = 0.f;
        for (int i = threadIdx.x; i < NW; i += 256)
            m = fmaxf(m, fabsf(w[i]));
        for (int o = 16; o; o >>= 1) m = fmaxf(m, __shfl_xor_sync(0xffffffffu, m, o));
        if ((threadIdx.x & 31) == 0) red[threadIdx.x >> 5] = m;
        __syncthreads();
        if (threadIdx.x < 32) {
            m = (threadIdx.x < 8) ? red[threadIdx.x] : 0.f;
            for (int o = 16; o; o >>= 1) m = fmaxf(m, __shfl_xor_sync(0xffffffffu, m, o));
            if (threadIdx.x == 0) {
                s_ma = (m > 0.f) ? m : 1.f;
                if (blockIdx.x == 0) g_maxabs = s_ma;   // for k_final
            }
        }
        __syncthreads();
        const float ma = s_ma;

        int idx = blockIdx.x * 256 + threadIdx.x;
        if (idx >= NOC * NGRP) return;
        int o = idx / NGRP, g = idx % NGRP;
        unsigned pw[4] = {0,0,0,0}, nw[4] = {0,0,0,0};
#pragma unroll
        for (int j = 0; j < 4; j++) {
            float r  = w[o * NFEAT + 4 * g + j];
            float wp = fmaxf(r, 0.f);
            float wn = fmaxf(-r, 0.f);
            int pi = (int)rintf(__fdiv_rn(wp, ma) * 255.f);
            int ni = (int)rintf(__fdiv_rn(wn, ma) * 255.f);
#pragma unroll
            for (int t = 0; t < 4; t++) {
                pw[t] |= (unsigned)((pi >> (2 * t)) & 3) << (8 * j);
                nw[t] |= (unsigned)((ni >> (2 * t)) & 3) << (8 * j);
            }
        }
#pragma unroll
        for (int t = 0; t < 4; t++) {
            g_wpos[o * NFEAT + t * NGRP + g] = pw[t];
            g_wneg[o * NFEAT + t * NGRP + g] = nw[t];
        }
    } else {
        // ---- stream packing from pre-quantized bytes (no float math) ----
        int id = (blockIdx.x - WB) * 256 + threadIdx.x;   // NPT*NGRP
        if (id >= NPT * NGRP) return;
        int pt = id & (NPT - 1);
        int g  = id >> 12;
        int b = pt >> 10, p = pt & 1023, h = p >> 5, wc = p & 31;
        unsigned sw0 = 0, sw1 = 0, sw2 = 0, sw3 = 0;
#pragma unroll
        for (int j = 0; j < 4; j++) {
            int f = 4 * g + j;
            int c = f / 9, rem = f - 9 * c, kh = rem / 3, kw = rem - 3 * (rem / 3);
            unsigned q = g_q[((b * 64 + c) * 34 + h + kh) * 34 + (wc + kw)];
            sw0 |= ( q        & 3u) << (8 * j);
            sw1 |= ((q >> 2)  & 3u) << (8 * j);
            sw2 |= ((q >> 4)  & 3u) << (8 * j);
            sw3 |= ((q >> 6)  & 3u) << (8 * j);
        }
        g_sv2[g * NPT + pt] = make_uint4(sw0, sw1, sw2, sw3);
    }
}

// ---------------------------------------------------------- main dp4a MAC
// grid (NPT/PTB, NOC/OBLK, NCH). Proven R14 core; result via atomicAdd.
__global__ __launch_bounds__(PTB, 5) void k_main() {
    __shared__ unsigned s_w[OBLK][29][8];    // [ol][gl][pos t0..3 | neg t0..3]
    const int tid   = threadIdx.x;
    const int pt    = blockIdx.x * PTB + tid;
    const int obase = blockIdx.y * OBLK;
    const int c     = blockIdx.z;
    const int g0    = c * 29;
    const int ng    = (c == 4) ? 28 : 29;

    for (int i = tid; i < OBLK * 29 * 8; i += PTB) {
        int r = i & 7, rest = i >> 3;
        int gl = rest % 29, ol = rest / 29;
        unsigned v = 0;
        if (gl < ng) {
            const unsigned* src = (r < 4) ? g_wpos : g_wneg;
            v = src[(obase + ol) * NFEAT + (r & 3) * NGRP + g0 + gl];
        }
        s_w[ol][gl][r] = v;   // zero rows for gl >= ng
    }
    __syncthreads();

    const uint4* __restrict__ sv = g_sv2 + g0 * NPT + pt;

    int accp[OBLK][16], accn[OBLK][16];
#pragma unroll
    for (int ol = 0; ol < OBLK; ol++)
#pragma unroll
        for (int i = 0; i < 16; i++) { accp[ol][i] = 0; accn[ol][i] = 0; }

    uint4 abuf[4];
    abuf[0] = sv[0 * NPT];
    abuf[1] = sv[1 * NPT];
    abuf[2] = sv[2 * NPT];

#pragma unroll
    for (int gl = 0; gl < 29; gl++) {
        abuf[(gl + 3) & 3] = sv[(gl + 3) * NPT];     // prefetch 3 ahead
        const uint4 a = abuf[gl & 3];
        const unsigned av[4] = {a.x, a.y, a.z, a.w};
        uint4 wp0 = *reinterpret_cast<const uint4*>(&s_w[0][gl][0]);
        uint4 wn0 = *reinterpret_cast<const uint4*>(&s_w[0][gl][4]);
        uint4 wp1 = *reinterpret_cast<const uint4*>(&s_w[1][gl][0]);
        uint4 wn1 = *reinterpret_cast<const uint4*>(&s_w[1][gl][4]);
        const unsigned pv0[4] = {wp0.x, wp0.y, wp0.z, wp0.w};
        const unsigned nv0[4] = {wn0.x, wn0.y, wn0.z, wn0.w};
        const unsigned pv1[4] = {wp1.x, wp1.y, wp1.z, wp1.w};
        const unsigned nv1[4] = {wn1.x, wn1.y, wn1.z, wn1.w};
#pragma unroll
        for (int s = 0; s < 4; s++)
#pragma unroll
            for (int t = 0; t < 4; t++) {
                accp[0][s * 4 + t] = __dp4a((int)av[s], (int)pv0[t], accp[0][s * 4 + t]);
                accn[0][s * 4 + t] = __dp4a((int)av[s], (int)nv0[t], accn[0][s * 4 + t]);
                accp[1][s * 4 + t] = __dp4a((int)av[s], (int)pv1[t], accp[1][s * 4 + t]);
                accn[1][s * 4 + t] = __dp4a((int)av[s], (int)nv1[t], accn[1][s * 4 + t]);
            }
    }

#pragma unroll
    for (int ol = 0; ol < OBLK; ol++) {
        int diff = 0;
#pragma unroll
        for (int s = 0; s < 4; s++)
#pragma unroll
            for (int t = 0; t < 4; t++)
                diff += (min(accp[ol][s * 4 + t], 31) - min(accn[ol][s * 4 + t], 31))
                        << (2 * (s + t));
        atomicAdd(&g_acc[((obase + ol) << 12) + pt], diff);   // REDG, distinct addrs
    }
}

// -------- scale accumulated diffs (4 pts/thread) + tail zero
#define FIN_MAIN (NOC * NPT / 4)   // 65536 vector items
__global__ void k_final(float* __restrict__ out, int out_size) {
    int id = blockIdx.x * blockDim.x + threadIdx.x;
    if (id < FIN_MAIN) {
        int oc  = id >> 10;               // 1024 vec per oc
        int ptv = (id & 1023) << 2;       // first of 4 consecutive pts
        int b = ptv >> 10, p = ptv & 1023;
        int4 d = *(const int4*)&g_acc[(oc << 12) + ptv];
        float sc = g_maxabs * (1.0f / 255.0f);
        float4 o = make_float4((float)d.x * sc, (float)d.y * sc,
                               (float)d.z * sc, (float)d.w * sc);
        *(float4*)&out[((b * NOC + oc) << 10) + p] = o;
    } else {
        int t = NOC * NPT + (id - FIN_MAIN);
        if (t < out_size) out[t] = 0.f;   // aux-loss scalar / padding tail
    }
}

extern "C" void kernel_launch(void* const* d_in, const int* in_sizes, int n_in,
                              void* d_out, int out_size) {
    const float* x = (const float*)d_in[0];   // inputs (4,64,32,32)
    const float* w = (const float*)d_in[1];   // weight (64,64,3,3)
    float* out = (float*)d_out;

    k_quant <<<QB + ZB, 256>>>(x);
    k_prep  <<<WB + SB, 256>>>(w);
    k_main  <<<dim3(NPT / PTB, NOC / OBLK, NCH), PTB>>>();
    int extra = (out_size > NOC * NPT) ? (out_size - NOC * NPT) : 0;
    k_final <<<(FIN_MAIN + extra + 255) / 256, 256>>>(out, out_size);
}

// round 16
// speedup vs baseline: 1.0271x; 1.0271x over previous
#include <cuda_runtime.h>

// Problem constants
#define NPT   4096      // B*H*W = 4*32*32 output points
#define NOC   64        // output channels
#define NFEAT 576       // IC*K*K unfolded features
#define NGRP  144       // 4-feature groups
#define NGRP_PAD 160    // padded so prefetch beyond last chunk stays in bounds
#define NCH   5         // subarray chunks (29,29,29,29,28 groups)
#define OBLK  2         // output channels per block in main kernel
#define PTB   128       // points per block (threads)
#define NW    (NOC * NFEAT)   // 36864 weight elements

// Scratch (no allocations allowed -> device globals)
__device__ float    g_maxabs;
__device__ unsigned g_wpos[NOC * NFEAT];        // [o][t][g]
__device__ unsigned g_wneg[NOC * NFEAT];
__device__ uint4    g_sv2[NGRP_PAD * NPT];      // [g][pt]; pads never consumed
__device__ int      g_acc[NOC * NPT];           // atomically accumulated diffs

// ---------------- fused prep: maxabs + weight slicing + streams + zero acc
// blocks [0, WB): weights (compute maxabs inline)
// blocks [WB, WB+SB): input bit-streaming (SWAR packing)
// blocks [WB+SB, WB+SB+ZB): zero g_acc
#define WB ((NOC * NGRP + 255) / 256)              // 36
#define SB ((NPT * NGRP + 255) / 256)              // 2304
#define ZB (NOC * NPT / (256 * 4))                 // 256
__global__ void k_prep(const float* __restrict__ w, const float* __restrict__ x) {
    if (blockIdx.x < WB) {
        // ---- per-block maxabs reduction over the full weight tensor ----
        __shared__ float red[32];
        __shared__ float s_ma;
        float m = 0.f;
        for (int i = threadIdx.x; i < NW; i += 256)
            m = fmaxf(m, fabsf(w[i]));
        for (int o = 16; o; o >>= 1) m = fmaxf(m, __shfl_xor_sync(0xffffffffu, m, o));
        if ((threadIdx.x & 31) == 0) red[threadIdx.x >> 5] = m;
        __syncthreads();
        if (threadIdx.x < 32) {
            m = (threadIdx.x < 8) ? red[threadIdx.x] : 0.f;
            for (int o = 16; o; o >>= 1) m = fmaxf(m, __shfl_xor_sync(0xffffffffu, m, o));
            if (threadIdx.x == 0) {
                s_ma = (m > 0.f) ? m : 1.f;
                if (blockIdx.x == 0) g_maxabs = s_ma;   // for k_final
            }
        }
        __syncthreads();
        const float ma = s_ma;

        int idx = blockIdx.x * 256 + threadIdx.x;
        if (idx >= NOC * NGRP) return;
        int o = idx / NGRP, g = idx % NGRP;
        unsigned pw[4] = {0,0,0,0}, nw[4] = {0,0,0,0};
#pragma unroll
        for (int j = 0; j < 4; j++) {
            float r  = w[o * NFEAT + 4 * g + j];
            float wp = fmaxf(r, 0.f);
            float wn = fmaxf(-r, 0.f);
            int pi = (int)rintf(__fdiv_rn(wp, ma) * 255.f);
            int ni = (int)rintf(__fdiv_rn(wn, ma) * 255.f);
#pragma unroll
            for (int t = 0; t < 4; t++) {
                pw[t] |= (unsigned)((pi >> (2 * t)) & 3) << (8 * j);
                nw[t] |= (unsigned)((ni >> (2 * t)) & 3) << (8 * j);
            }
        }
#pragma unroll
        for (int t = 0; t < 4; t++) {
            g_wpos[o * NFEAT + t * NGRP + g] = pw[t];
            g_wneg[o * NFEAT + t * NGRP + g] = nw[t];
        }
    } else if (blockIdx.x < WB + SB) {
        int id = (blockIdx.x - WB) * 256 + threadIdx.x;   // NPT*NGRP
        if (id >= NPT * NGRP) return;
        int pt = id & (NPT - 1);
        int g  = id >> 12;
        int b = pt >> 10, p = pt & 1023, h = p >> 5, wc = p & 31;
        unsigned Q = 0;   // 4 quantized bytes, one per feature j
#pragma unroll
        for (int j = 0; j < 4; j++) {
            int f = 4 * g + j;
            int c = f / 9, rem = f - 9 * c, kh = rem / 3, kw = rem - 3 * (rem / 3);
            int y = h + kh - 1, xx = wc + kw - 1;
            float v = 0.f;
            if ((unsigned)y < 32u && (unsigned)xx < 32u)
                v = x[((b * 64 + c) * 32 + y) * 32 + xx];
            v = fminf(fmaxf(v, -8.f), 7.9375f);
            Q |= (unsigned)(((int)rintf(v * 16.f)) & 255) << (8 * j);
        }
        // SWAR extraction: stream s = bits [2s,2s+2) of every byte
        unsigned sw0 =  Q        & 0x03030303u;
        unsigned sw1 = (Q >> 2)  & 0x03030303u;
        unsigned sw2 = (Q >> 4)  & 0x03030303u;
        unsigned sw3 = (Q >> 6)  & 0x03030303u;
        g_sv2[g * NPT + pt] = make_uint4(sw0, sw1, sw2, sw3);
    } else {
        // zero the accumulator (int4 stores)
        int id = (blockIdx.x - WB - SB) * 256 + threadIdx.x;
        if (id < NOC * NPT / 4)
            *(int4*)&g_acc[id * 4] = make_int4(0, 0, 0, 0);
    }
}

// ---------------------------------------------------------- main dp4a MAC
// grid (NPT/PTB, NOC/OBLK, NCH). Proven R14 core; result via atomicAdd.
__global__ __launch_bounds__(PTB, 5) void k_main() {
    __shared__ unsigned s_w[OBLK][29][8];    // [ol][gl][pos t0..3 | neg t0..3]
    const int tid   = threadIdx.x;
    const int pt    = blockIdx.x * PTB + tid;
    const int obase = blockIdx.y * OBLK;
    const int c     = blockIdx.z;
    const int g0    = c * 29;
    const int ng    = (c == 4) ? 28 : 29;

    for (int i = tid; i < OBLK * 29 * 8; i += PTB) {
        int r = i & 7, rest = i >> 3;
        int gl = rest % 29, ol = rest / 29;
        unsigned v = 0;
        if (gl < ng) {
            const unsigned* src = (r < 4) ? g_wpos : g_wneg;
            v = src[(obase + ol) * NFEAT + (r & 3) * NGRP + g0 + gl];
        }
        s_w[ol][gl][r] = v;   // zero rows for gl >= ng
    }
    __syncthreads();

    const uint4* __restrict__ sv = g_sv2 + g0 * NPT + pt;

    int accp[OBLK][16], accn[OBLK][16];
#pragma unroll
    for (int ol = 0; ol < OBLK; ol++)
#pragma unroll
        for (int i = 0; i < 16; i++) { accp[ol][i] = 0; accn[ol][i] = 0; }

    uint4 abuf[4];
    abuf[0] = sv[0 * NPT];
    abuf[1] = sv[1 * NPT];
    abuf[2] = sv[2 * NPT];

#pragma unroll
    for (int gl = 0; gl < 29; gl++) {
        abuf[(gl + 3) & 3] = sv[(gl + 3) * NPT];     // prefetch 3 ahead
        const uint4 a = abuf[gl & 3];
        const unsigned av[4] = {a.x, a.y, a.z, a.w};
        uint4 wp0 = *reinterpret_cast<const uint4*>(&s_w[0][gl][0]);
        uint4 wn0 = *reinterpret_cast<const uint4*>(&s_w[0][gl][4]);
        uint4 wp1 = *reinterpret_cast<const uint4*>(&s_w[1][gl][0]);
        uint4 wn1 = *reinterpret_cast<const uint4*>(&s_w[1][gl][4]);
        const unsigned pv0[4] = {wp0.x, wp0.y, wp0.z, wp0.w};
        const unsigned nv0[4] = {wn0.x, wn0.y, wn0.z, wn0.w};
        const unsigned pv1[4] = {wp1.x, wp1.y, wp1.z, wp1.w};
        const unsigned nv1[4] = {wn1.x, wn1.y, wn1.z, wn1.w};
#pragma unroll
        for (int s = 0; s < 4; s++)
#pragma unroll
            for (int t = 0; t < 4; t++) {
                accp[0][s * 4 + t] = __dp4a((int)av[s], (int)pv0[t], accp[0][s * 4 + t]);
                accn[0][s * 4 + t] = __dp4a((int)av[s], (int)nv0[t], accn[0][s * 4 + t]);
                accp[1][s * 4 + t] = __dp4a((int)av[s], (int)pv1[t], accp[1][s * 4 + t]);
                accn[1][s * 4 + t] = __dp4a((int)av[s], (int)nv1[t], accn[1][s * 4 + t]);
            }
    }

#pragma unroll
    for (int ol = 0; ol < OBLK; ol++) {
        int diff = 0;
#pragma unroll
        for (int s = 0; s < 4; s++)
#pragma unroll
            for (int t = 0; t < 4; t++)
                diff += (min(accp[ol][s * 4 + t], 31) - min(accn[ol][s * 4 + t], 31))
                        << (2 * (s + t));
        atomicAdd(&g_acc[((obase + ol) << 12) + pt], diff);   // REDG, distinct addrs
    }
}

// -------- scale accumulated diffs (scalar: max parallelism) + tail zero
__global__ void k_final(float* __restrict__ out, int out_size) {
    int id = blockIdx.x * blockDim.x + threadIdx.x;
    if (id < NOC * NPT) {
        int oc = id >> 12, pt = id & (NPT - 1);
        int b = pt >> 10, p = pt & 1023;
        out[((b * NOC + oc) << 10) + p] =
            (float)g_acc[id] * (g_maxabs * (1.0f / 255.0f));
    } else if (id < out_size) {
        out[id] = 0.f;   // aux-loss scalar / padding tail
    }
}

extern "C" void kernel_launch(void* const* d_in, const int* in_sizes, int n_in,
                              void* d_out, int out_size) {
    const float* x = (const float*)d_in[0];   // inputs (4,64,32,32)
    const float* w = (const float*)d_in[1];   // weight (64,64,3,3)
    float* out = (float*)d_out;

    k_prep  <<<WB + SB + ZB, 256>>>(w, x);
    k_main  <<<dim3(NPT / PTB, NOC / OBLK, NCH), PTB>>>();
    int fin = (out_size > NOC * NPT) ? out_size : NOC * NPT;
    k_final <<<(fin + 255) / 256, 256>>>(out, out_size);
}